// round 1
// baseline (speedup 1.0000x reference)
#include <cuda_runtime.h>

#define HIDN 1024
#define BB 16
#define SS 1024
#define HH 16
#define DD 64
#define NTOK (BB*SS)

// Scratch (allocation-free rule: __device__ globals)
__device__ float g_q[NTOK * HIDN];
__device__ float g_k[NTOK * HIDN];
__device__ float g_v[NTOK * HIDN];
__device__ float g_ctx[NTOK * HIDN];

// ---------------------------------------------------------------------------
// GEMM: C[M,N] = A[M,K] @ W[N,K]^T + bias[N]   (M=16384, N=K=1024)
// Optionally fuses hs = hidden + pos(s)*W_pe + b_pe into the A-tile load.
// blockIdx.z selects (W, bias, C) triple (QKV fused in one launch).
// ---------------------------------------------------------------------------
template<bool FUSE_POS>
__global__ __launch_bounds__(256)
void gemm_nt(const float* __restrict__ A,
             const float* __restrict__ W0, const float* __restrict__ b0, float* __restrict__ C0,
             const float* __restrict__ W1, const float* __restrict__ b1, float* __restrict__ C1,
             const float* __restrict__ W2, const float* __restrict__ b2, float* __restrict__ C2,
             const float* __restrict__ Wpe, const float* __restrict__ bpe)
{
    const float* W; const float* bias; float* C;
    if (blockIdx.z == 0)      { W = W0; bias = b0; C = C0; }
    else if (blockIdx.z == 1) { W = W1; bias = b1; C = C1; }
    else                      { W = W2; bias = b2; C = C2; }

    __shared__ float As[8][132];
    __shared__ float Ws[8][132];

    const int tid = threadIdx.x;
    const int tx = tid & 15;      // 0..15 -> n microtile
    const int ty = tid >> 4;      // 0..15 -> m microtile
    const int m0 = blockIdx.y * 128;
    const int n0 = blockIdx.x * 128;

    const int lr = tid >> 1;        // 0..127 row within tile
    const int lk = (tid & 1) * 4;   // 0 or 4

    float acc[8][8];
#pragma unroll
    for (int i = 0; i < 8; i++)
#pragma unroll
        for (int j = 0; j < 8; j++) acc[i][j] = 0.0f;

    for (int kt = 0; kt < HIDN; kt += 8) {
        float4 av = *(const float4*)(A + (size_t)(m0 + lr) * HIDN + kt + lk);
        if (FUSE_POS) {
            int s = (m0 + lr) & (SS - 1);
            float posv = (float)(s - SS / 2) * (1.0f / (512.0f + 1e-6f));
            float4 wp = *(const float4*)(Wpe + kt + lk);
            float4 bp = *(const float4*)(bpe + kt + lk);
            av.x += posv * wp.x + bp.x;
            av.y += posv * wp.y + bp.y;
            av.z += posv * wp.z + bp.z;
            av.w += posv * wp.w + bp.w;
        }
        As[lk + 0][lr] = av.x; As[lk + 1][lr] = av.y;
        As[lk + 2][lr] = av.z; As[lk + 3][lr] = av.w;

        float4 wv = *(const float4*)(W + (size_t)(n0 + lr) * HIDN + kt + lk);
        Ws[lk + 0][lr] = wv.x; Ws[lk + 1][lr] = wv.y;
        Ws[lk + 2][lr] = wv.z; Ws[lk + 3][lr] = wv.w;

        __syncthreads();

#pragma unroll
        for (int k = 0; k < 8; k++) {
            float4 a0 = *(const float4*)&As[k][ty * 8];
            float4 a1 = *(const float4*)&As[k][ty * 8 + 4];
            float4 b0v = *(const float4*)&Ws[k][tx * 8];
            float4 b1v = *(const float4*)&Ws[k][tx * 8 + 4];
            float ar[8] = {a0.x, a0.y, a0.z, a0.w, a1.x, a1.y, a1.z, a1.w};
            float br[8] = {b0v.x, b0v.y, b0v.z, b0v.w, b1v.x, b1v.y, b1v.z, b1v.w};
#pragma unroll
            for (int i = 0; i < 8; i++)
#pragma unroll
                for (int j = 0; j < 8; j++)
                    acc[i][j] += ar[i] * br[j];
        }
        __syncthreads();
    }

    float bn[8];
#pragma unroll
    for (int j = 0; j < 8; j++) bn[j] = bias[n0 + tx * 8 + j];

#pragma unroll
    for (int i = 0; i < 8; i++) {
        float4 c0 = make_float4(acc[i][0] + bn[0], acc[i][1] + bn[1],
                                acc[i][2] + bn[2], acc[i][3] + bn[3]);
        float4 c1 = make_float4(acc[i][4] + bn[4], acc[i][5] + bn[5],
                                acc[i][6] + bn[6], acc[i][7] + bn[7]);
        float* Crow = C + (size_t)(m0 + ty * 8 + i) * HIDN + n0 + tx * 8;
        *(float4*)(Crow)     = c0;
        *(float4*)(Crow + 4) = c1;
    }
}

// ---------------------------------------------------------------------------
// Flash attention (fp32), BQ=128, BK=64, D=64.
// grid: (S/128, H, B).  scores = (Q*K^T)/8 + pos_bias[h, key]  (key-only bias)
// ---------------------------------------------------------------------------
__global__ __launch_bounds__(256)
void attn_kernel(const float* __restrict__ Q, const float* __restrict__ K,
                 const float* __restrict__ V, const float* __restrict__ pos_bias,
                 float* __restrict__ ctx)
{
    extern __shared__ float sm[];
    float* Qt = sm;                    // [64][128]  d-major
    float* Kt = Qt + 64 * 128;         // [64][64]   d-major
    float* Vs = Kt + 64 * 64;          // [64][68]   key-major (padded)
    float* Ps = Vs + 64 * 68;          // [128][68]  q-major (padded)
    float* bs = Ps + 128 * 68;         // [64]

    const int tid = threadIdx.x;
    const int tx = tid & 15;           // k/d microtile (4-wide)
    const int ty = tid >> 4;           // q microtile (8-wide)
    const int q0 = blockIdx.x * 128;
    const int h = blockIdx.y, b = blockIdx.z;
    const size_t base = ((size_t)b * SS) * HIDN + h * DD;

    // Load Q tile (scaled by 1/sqrt(D)=0.125), transposed to d-major
#pragma unroll
    for (int f = 0; f < 8; f++) {
        int fidx = tid * 8 + f;        // 0..2047
        int r = fidx >> 4;
        int dq = (fidx & 15) * 4;
        float4 qv = *(const float4*)(Q + base + (size_t)(q0 + r) * HIDN + dq);
        Qt[(dq + 0) * 128 + r] = qv.x * 0.125f;
        Qt[(dq + 1) * 128 + r] = qv.y * 0.125f;
        Qt[(dq + 2) * 128 + r] = qv.z * 0.125f;
        Qt[(dq + 3) * 128 + r] = qv.w * 0.125f;
    }

    float m[8], l[8], o[8][4];
#pragma unroll
    for (int i = 0; i < 8; i++) {
        m[i] = -1e30f; l[i] = 0.0f;
#pragma unroll
        for (int j = 0; j < 4; j++) o[i][j] = 0.0f;
    }

    for (int kt0 = 0; kt0 < SS; kt0 += 64) {
        __syncthreads();   // protect Kt/Vs/Ps from previous iteration (and Qt store)
        // Load K (transposed to d-major) and V (key-major) tiles: 64x64 each
#pragma unroll
        for (int f = 0; f < 4; f++) {
            int fidx = tid * 4 + f;    // 0..1023
            int r = fidx >> 4;
            int dq = (fidx & 15) * 4;
            float4 kv = *(const float4*)(K + base + (size_t)(kt0 + r) * HIDN + dq);
            Kt[(dq + 0) * 64 + r] = kv.x;
            Kt[(dq + 1) * 64 + r] = kv.y;
            Kt[(dq + 2) * 64 + r] = kv.z;
            Kt[(dq + 3) * 64 + r] = kv.w;
            float4 vv = *(const float4*)(V + base + (size_t)(kt0 + r) * HIDN + dq);
            *(float4*)&Vs[r * 68 + dq] = vv;
        }
        if (tid < 64) bs[tid] = pos_bias[h * 1025 + kt0 + tid];
        __syncthreads();

        // S = Qt^T Kt  (scaled already), 8x4 per thread
        float sv[8][4];
#pragma unroll
        for (int i = 0; i < 8; i++)
#pragma unroll
            for (int j = 0; j < 4; j++) sv[i][j] = 0.0f;

#pragma unroll 8
        for (int d = 0; d < 64; d++) {
            float4 qa = *(const float4*)&Qt[d * 128 + ty * 8];
            float4 qb = *(const float4*)&Qt[d * 128 + ty * 8 + 4];
            float4 kv = *(const float4*)&Kt[d * 64 + tx * 4];
            float qr[8] = {qa.x, qa.y, qa.z, qa.w, qb.x, qb.y, qb.z, qb.w};
            float kr[4] = {kv.x, kv.y, kv.z, kv.w};
#pragma unroll
            for (int i = 0; i < 8; i++)
#pragma unroll
                for (int j = 0; j < 4; j++)
                    sv[i][j] += qr[i] * kr[j];
        }

        // + key bias
        float bj[4];
#pragma unroll
        for (int j = 0; j < 4; j++) bj[j] = bs[tx * 4 + j];
#pragma unroll
        for (int i = 0; i < 8; i++)
#pragma unroll
            for (int j = 0; j < 4; j++) sv[i][j] += bj[j];

        // online softmax update
#pragma unroll
        for (int i = 0; i < 8; i++) {
            float rmax = sv[i][0];
#pragma unroll
            for (int j = 1; j < 4; j++) rmax = fmaxf(rmax, sv[i][j]);
#pragma unroll
            for (int off = 1; off < 16; off <<= 1)
                rmax = fmaxf(rmax, __shfl_xor_sync(0xffffffffu, rmax, off));
            float mnew = fmaxf(m[i], rmax);
            float fac = __expf(m[i] - mnew);
            float rsum = 0.0f;
#pragma unroll
            for (int j = 0; j < 4; j++) {
                float p = __expf(sv[i][j] - mnew);
                sv[i][j] = p;
                rsum += p;
            }
#pragma unroll
            for (int off = 1; off < 16; off <<= 1)
                rsum += __shfl_xor_sync(0xffffffffu, rsum, off);
            l[i] = l[i] * fac + rsum;
            m[i] = mnew;
#pragma unroll
            for (int j = 0; j < 4; j++) o[i][j] *= fac;
            *(float4*)&Ps[(ty * 8 + i) * 68 + tx * 4] =
                make_float4(sv[i][0], sv[i][1], sv[i][2], sv[i][3]);
        }
        __syncthreads();

        // O += P @ V
#pragma unroll 4
        for (int kk2 = 0; kk2 < 64; kk2++) {
            float4 vv = *(const float4*)&Vs[kk2 * 68 + tx * 4];
            float vr[4] = {vv.x, vv.y, vv.z, vv.w};
#pragma unroll
            for (int i = 0; i < 8; i++) {
                float p = Ps[(ty * 8 + i) * 68 + kk2];
#pragma unroll
                for (int j = 0; j < 4; j++) o[i][j] += p * vr[j];
            }
        }
    }

    // epilogue: normalize and write ctx [b, s, h*64 + d]
#pragma unroll
    for (int i = 0; i < 8; i++) {
        float inv = 1.0f / l[i];
        float4 c = make_float4(o[i][0] * inv, o[i][1] * inv,
                               o[i][2] * inv, o[i][3] * inv);
        *(float4*)(ctx + base + (size_t)(q0 + ty * 8 + i) * HIDN + tx * 4) = c;
    }
}

// ---------------------------------------------------------------------------
extern "C" void kernel_launch(void* const* d_in, const int* in_sizes, int n_in,
                              void* d_out, int out_size)
{
    const float* hidden = (const float*)d_in[0];
    const float* Wq = (const float*)d_in[1];  const float* bq = (const float*)d_in[2];
    const float* Wk = (const float*)d_in[3];  const float* bk = (const float*)d_in[4];
    const float* Wv = (const float*)d_in[5];  const float* bv = (const float*)d_in[6];
    const float* Wo = (const float*)d_in[7];  const float* bo = (const float*)d_in[8];
    const float* Wpe = (const float*)d_in[9]; const float* bpe = (const float*)d_in[10];
    const float* pos_bias = (const float*)d_in[11];
    float* out = (float*)d_out;

    float *dq, *dk, *dv, *dctx;
    cudaGetSymbolAddress((void**)&dq, g_q);
    cudaGetSymbolAddress((void**)&dk, g_k);
    cudaGetSymbolAddress((void**)&dv, g_v);
    cudaGetSymbolAddress((void**)&dctx, g_ctx);

    const size_t ATTN_SMEM = (size_t)(64 * 128 + 64 * 64 + 64 * 68 + 128 * 68 + 64) * sizeof(float);
    cudaFuncSetAttribute(attn_kernel, cudaFuncAttributeMaxDynamicSharedMemorySize, (int)ATTN_SMEM);

    dim3 blk(256);
    // fused QKV projection (z = 0,1,2)
    gemm_nt<true><<<dim3(8, 128, 3), blk>>>(hidden,
                                            Wq, bq, dq,
                                            Wk, bk, dk,
                                            Wv, bv, dv,
                                            Wpe, bpe);
    // attention
    attn_kernel<<<dim3(8, HH, BB), blk, ATTN_SMEM>>>(dq, dk, dv, pos_bias, dctx);
    // output projection
    gemm_nt<false><<<dim3(8, 128, 1), blk>>>(dctx,
                                             Wo, bo, out,
                                             Wo, bo, out,
                                             Wo, bo, out,
                                             nullptr, nullptr);
}

// round 3
// speedup vs baseline: 1.6264x; 1.6264x over previous
#include <cuda_runtime.h>
#include <cuda_bf16.h>
#include <cstdint>

#define HIDN 1024
#define BB 16
#define SS 1024
#define HH 16
#define DD 64
#define NTOK (BB*SS)
#define KE 2048   // [hi | lo] physical layout

// ---------------- scratch (__device__ globals, allocation-free rule) -------
__device__ float g_q[NTOK * HIDN];
__device__ float g_k[NTOK * HIDN];
__device__ float g_v[NTOK * HIDN];
__device__ float g_ctx[NTOK * HIDN];
__device__ __nv_bfloat16 g_ae[(size_t)NTOK * KE];
__device__ __nv_bfloat16 g_ce[(size_t)NTOK * KE];
__device__ __nv_bfloat16 g_we[4][(size_t)HIDN * KE];

// ---------------- helpers ---------------------------------------------------
__device__ __forceinline__ uint32_t smem_u32(const void* p) {
    uint32_t a;
    asm("{ .reg .u64 t; cvta.to.shared.u64 t, %1; cvt.u32.u64 %0, t; }" : "=r"(a) : "l"(p));
    return a;
}
__device__ __forceinline__ void ldsm_x4(uint32_t& r0, uint32_t& r1, uint32_t& r2,
                                        uint32_t& r3, uint32_t a) {
    asm volatile("ldmatrix.sync.aligned.m8n8.x4.shared.b16 {%0,%1,%2,%3}, [%4];"
                 : "=r"(r0), "=r"(r1), "=r"(r2), "=r"(r3) : "r"(a));
}
__device__ __forceinline__ void mma16816(float* c, const uint32_t* a, const uint32_t* b) {
    asm volatile("mma.sync.aligned.m16n8k16.row.col.f32.bf16.bf16.f32 "
                 "{%0,%1,%2,%3}, {%4,%5,%6,%7}, {%8,%9}, {%0,%1,%2,%3};"
                 : "+f"(c[0]), "+f"(c[1]), "+f"(c[2]), "+f"(c[3])
                 : "r"(a[0]), "r"(a[1]), "r"(a[2]), "r"(a[3]), "r"(b[0]), "r"(b[1]));
}

// ---------------------------------------------------------------------------
// Conversion kernels: fp32 -> [hi | lo] bf16 split (lo = x - bf16(x))
// ---------------------------------------------------------------------------
template<bool FUSE_POS>
__global__ void prep_a(const float* __restrict__ src, const float* __restrict__ wpe,
                       const float* __restrict__ bpe, __nv_bfloat16* __restrict__ E)
{
    int m = blockIdx.x;
    int k = threadIdx.x * 4;
    float4 v = *(const float4*)(src + (size_t)m * HIDN + k);
    if (FUSE_POS) {
        float posv = (float)((m & (SS - 1)) - SS / 2) * (1.0f / (512.0f + 1e-6f));
        float4 wp = *(const float4*)(wpe + k);
        float4 bp = *(const float4*)(bpe + k);
        v.x += posv * wp.x + bp.x;  v.y += posv * wp.y + bp.y;
        v.z += posv * wp.z + bp.z;  v.w += posv * wp.w + bp.w;
    }
    float a[4] = {v.x, v.y, v.z, v.w};
    __nv_bfloat16* hi = E + (size_t)m * KE + k;
    __nv_bfloat16* lo = hi + HIDN;
#pragma unroll
    for (int j = 0; j < 4; j++) {
        __nv_bfloat16 hb = __float2bfloat16(a[j]);
        hi[j] = hb;
        lo[j] = __float2bfloat16(a[j] - __bfloat162float(hb));
    }
}

__global__ void prep_w(const float* __restrict__ W0, const float* __restrict__ W1,
                       const float* __restrict__ W2, const float* __restrict__ W3,
                       __nv_bfloat16* __restrict__ E0, __nv_bfloat16* __restrict__ E1,
                       __nv_bfloat16* __restrict__ E2, __nv_bfloat16* __restrict__ E3)
{
    const float* W; __nv_bfloat16* E;
    switch (blockIdx.z) {
        case 0: W = W0; E = E0; break;
        case 1: W = W1; E = E1; break;
        case 2: W = W2; E = E2; break;
        default: W = W3; E = E3; break;
    }
    int n = blockIdx.x;
    int k = threadIdx.x * 4;
    float4 v = *(const float4*)(W + (size_t)n * HIDN + k);
    float a[4] = {v.x, v.y, v.z, v.w};
    __nv_bfloat16* hi = E + (size_t)n * KE + k;
    __nv_bfloat16* lo = hi + HIDN;
#pragma unroll
    for (int j = 0; j < 4; j++) {
        __nv_bfloat16 hb = __float2bfloat16(a[j]);
        hi[j] = hb;
        lo[j] = __float2bfloat16(a[j] - __bfloat162float(hb));
    }
}

// ---------------------------------------------------------------------------
// HMMA GEMM: C[M,1024] = Ae @ We^T + bias  (bf16 hi/lo split, fp32 accum)
// CTA 128x128, 256 threads (warp grid 2x4 -> 64x32/warp), K-chunks of 64.
// 3 mma passes per chunk: Ah*Wh + Al*Wh + Ah*Wl.
// Smem: 4 tiles of [128][72] bf16 (pad 72 -> conflict-free ldmatrix).
// ---------------------------------------------------------------------------
#define LDA 72
#define T_AH 0
#define T_AL (128 * LDA)
#define T_WH (2 * 128 * LDA)
#define T_WL (3 * 128 * LDA)
#define GEMM_SMEM (4 * 128 * LDA * 2)

__global__ __launch_bounds__(256, 2)
void gemm_tc(const __nv_bfloat16* __restrict__ Ae,
             const __nv_bfloat16* __restrict__ W0e, const float* __restrict__ b0, float* __restrict__ C0,
             const __nv_bfloat16* __restrict__ W1e, const float* __restrict__ b1, float* __restrict__ C1,
             const __nv_bfloat16* __restrict__ W2e, const float* __restrict__ b2, float* __restrict__ C2)
{
    const __nv_bfloat16* We; const float* bias; float* C;
    if (blockIdx.z == 0)      { We = W0e; bias = b0; C = C0; }
    else if (blockIdx.z == 1) { We = W1e; bias = b1; C = C1; }
    else                      { We = W2e; bias = b2; C = C2; }

    extern __shared__ __align__(16) __nv_bfloat16 sm[];
    const uint32_t sb = smem_u32(sm);

    const int tid = threadIdx.x;
    const int lane = tid & 31;
    const int wid = tid >> 5;
    const int wm = wid & 1;        // m-warp (0..1) -> 64 rows
    const int wn = wid >> 1;       // n-warp (0..3) -> 32 cols
    const int m0 = blockIdx.y * 128;
    const int n0 = blockIdx.x * 128;

    // loader mapping: row = tid>>1 (0..127), half = tid&1 (32 bf16 = 4 x uint4)
    const int lrow = tid >> 1;
    const int lhalf = (tid & 1) * 32;
    const __nv_bfloat16* arow = Ae + (size_t)(m0 + lrow) * KE;
    const __nv_bfloat16* wrow = We + (size_t)(n0 + lrow) * KE;
    __nv_bfloat16* sAh = sm + T_AH + lrow * LDA + lhalf;
    __nv_bfloat16* sAl = sm + T_AL + lrow * LDA + lhalf;
    __nv_bfloat16* sWh = sm + T_WH + lrow * LDA + lhalf;
    __nv_bfloat16* sWl = sm + T_WL + lrow * LDA + lhalf;

    // ldmatrix per-lane address components (element offsets)
    const int aRow = (wm * 64 + (lane & 15)) * LDA + (lane >> 4) * 8;
    const int quad = lane >> 3;
    const int bRow = (wn * 32 + (quad >> 1) * 8 + (lane & 7)) * LDA + (quad & 1) * 8;

    float acc[4][4][4];
#pragma unroll
    for (int i = 0; i < 4; i++)
#pragma unroll
        for (int j = 0; j < 4; j++)
#pragma unroll
            for (int r = 0; r < 4; r++) acc[i][j][r] = 0.0f;

    for (int chunk = 0; chunk < 16; chunk++) {
        const int kb = chunk * 64;
        __syncthreads();
#pragma unroll
        for (int j = 0; j < 4; j++) {
            *(uint4*)(sAh + j * 8) = *(const uint4*)(arow + kb + lhalf + j * 8);
            *(uint4*)(sAl + j * 8) = *(const uint4*)(arow + HIDN + kb + lhalf + j * 8);
            *(uint4*)(sWh + j * 8) = *(const uint4*)(wrow + kb + lhalf + j * 8);
            *(uint4*)(sWl + j * 8) = *(const uint4*)(wrow + HIDN + kb + lhalf + j * 8);
        }
        __syncthreads();

#pragma unroll
        for (int ks = 0; ks < 4; ks++) {
            const int k0 = ks * 16;
            uint32_t aH[16];
#pragma unroll
            for (int fm = 0; fm < 4; fm++)
                ldsm_x4(aH[fm * 4 + 0], aH[fm * 4 + 1], aH[fm * 4 + 2], aH[fm * 4 + 3],
                        sb + 2 * (T_AH + aRow + fm * 16 * LDA + k0));
            {
                uint32_t bH[8];
#pragma unroll
                for (int fp = 0; fp < 2; fp++)
                    ldsm_x4(bH[fp * 4 + 0], bH[fp * 4 + 1], bH[fp * 4 + 2], bH[fp * 4 + 3],
                            sb + 2 * (T_WH + bRow + fp * 16 * LDA + k0));
#pragma unroll
                for (int fm = 0; fm < 4; fm++)
#pragma unroll
                    for (int fn = 0; fn < 4; fn++)
                        mma16816(acc[fm][fn], &aH[fm * 4], &bH[fn * 2]);
                // Al * Wh
                {
                    uint32_t aL[16];
#pragma unroll
                    for (int fm = 0; fm < 4; fm++)
                        ldsm_x4(aL[fm * 4 + 0], aL[fm * 4 + 1], aL[fm * 4 + 2], aL[fm * 4 + 3],
                                sb + 2 * (T_AL + aRow + fm * 16 * LDA + k0));
#pragma unroll
                    for (int fm = 0; fm < 4; fm++)
#pragma unroll
                        for (int fn = 0; fn < 4; fn++)
                            mma16816(acc[fm][fn], &aL[fm * 4], &bH[fn * 2]);
                }
            }
            // Ah * Wl
            {
                uint32_t bL[8];
#pragma unroll
                for (int fp = 0; fp < 2; fp++)
                    ldsm_x4(bL[fp * 4 + 0], bL[fp * 4 + 1], bL[fp * 4 + 2], bL[fp * 4 + 3],
                            sb + 2 * (T_WL + bRow + fp * 16 * LDA + k0));
#pragma unroll
                for (int fm = 0; fm < 4; fm++)
#pragma unroll
                    for (int fn = 0; fn < 4; fn++)
                        mma16816(acc[fm][fn], &aH[fm * 4], &bL[fn * 2]);
            }
        }
    }

    // epilogue: D-frag mapping: reg0:(m=t/4, n=2(t%4)), reg1:(m, n+1),
    //           reg2:(m+8, n), reg3:(m+8, n+1)
    const int rt = lane >> 2;
    const int ct = (lane & 3) * 2;
#pragma unroll
    for (int fn = 0; fn < 4; fn++) {
        const int gcol = n0 + wn * 32 + fn * 8 + ct;
        const float bn0 = __ldg(bias + gcol);
        const float bn1 = __ldg(bias + gcol + 1);
#pragma unroll
        for (int fm = 0; fm < 4; fm++) {
            const int grow = m0 + wm * 64 + fm * 16 + rt;
            float2 v0 = make_float2(acc[fm][fn][0] + bn0, acc[fm][fn][1] + bn1);
            float2 v1 = make_float2(acc[fm][fn][2] + bn0, acc[fm][fn][3] + bn1);
            *(float2*)(C + (size_t)grow * HIDN + gcol) = v0;
            *(float2*)(C + (size_t)(grow + 8) * HIDN + gcol) = v1;
        }
    }
}

// ---------------------------------------------------------------------------
// Flash attention (fp32) — unchanged (passing since round 1)
// ---------------------------------------------------------------------------
__global__ __launch_bounds__(256)
void attn_kernel(const float* __restrict__ Q, const float* __restrict__ K,
                 const float* __restrict__ V, const float* __restrict__ pos_bias,
                 float* __restrict__ ctx)
{
    extern __shared__ float sma[];
    float* Qt = sma;                   // [64][128]  d-major
    float* Kt = Qt + 64 * 128;         // [64][64]   d-major
    float* Vs = Kt + 64 * 64;          // [64][68]   key-major (padded)
    float* Ps = Vs + 64 * 68;          // [128][68]  q-major (padded)
    float* bs = Ps + 128 * 68;         // [64]

    const int tid = threadIdx.x;
    const int tx = tid & 15;
    const int ty = tid >> 4;
    const int q0 = blockIdx.x * 128;
    const int h = blockIdx.y, b = blockIdx.z;
    const size_t base = ((size_t)b * SS) * HIDN + h * DD;

#pragma unroll
    for (int f = 0; f < 8; f++) {
        int fidx = tid * 8 + f;
        int r = fidx >> 4;
        int dq = (fidx & 15) * 4;
        float4 qv = *(const float4*)(Q + base + (size_t)(q0 + r) * HIDN + dq);
        Qt[(dq + 0) * 128 + r] = qv.x * 0.125f;
        Qt[(dq + 1) * 128 + r] = qv.y * 0.125f;
        Qt[(dq + 2) * 128 + r] = qv.z * 0.125f;
        Qt[(dq + 3) * 128 + r] = qv.w * 0.125f;
    }

    float m[8], l[8], o[8][4];
#pragma unroll
    for (int i = 0; i < 8; i++) {
        m[i] = -1e30f; l[i] = 0.0f;
#pragma unroll
        for (int j = 0; j < 4; j++) o[i][j] = 0.0f;
    }

    for (int kt0 = 0; kt0 < SS; kt0 += 64) {
        __syncthreads();
#pragma unroll
        for (int f = 0; f < 4; f++) {
            int fidx = tid * 4 + f;
            int r = fidx >> 4;
            int dq = (fidx & 15) * 4;
            float4 kv = *(const float4*)(K + base + (size_t)(kt0 + r) * HIDN + dq);
            Kt[(dq + 0) * 64 + r] = kv.x;
            Kt[(dq + 1) * 64 + r] = kv.y;
            Kt[(dq + 2) * 64 + r] = kv.z;
            Kt[(dq + 3) * 64 + r] = kv.w;
            float4 vv = *(const float4*)(V + base + (size_t)(kt0 + r) * HIDN + dq);
            *(float4*)&Vs[r * 68 + dq] = vv;
        }
        if (tid < 64) bs[tid] = pos_bias[h * 1025 + kt0 + tid];
        __syncthreads();

        float sv[8][4];
#pragma unroll
        for (int i = 0; i < 8; i++)
#pragma unroll
            for (int j = 0; j < 4; j++) sv[i][j] = 0.0f;

#pragma unroll 8
        for (int d = 0; d < 64; d++) {
            float4 qa = *(const float4*)&Qt[d * 128 + ty * 8];
            float4 qb = *(const float4*)&Qt[d * 128 + ty * 8 + 4];
            float4 kv = *(const float4*)&Kt[d * 64 + tx * 4];
            float qr[8] = {qa.x, qa.y, qa.z, qa.w, qb.x, qb.y, qb.z, qb.w};
            float kr[4] = {kv.x, kv.y, kv.z, kv.w};
#pragma unroll
            for (int i = 0; i < 8; i++)
#pragma unroll
                for (int j = 0; j < 4; j++)
                    sv[i][j] += qr[i] * kr[j];
        }

        float bj[4];
#pragma unroll
        for (int j = 0; j < 4; j++) bj[j] = bs[tx * 4 + j];
#pragma unroll
        for (int i = 0; i < 8; i++)
#pragma unroll
            for (int j = 0; j < 4; j++) sv[i][j] += bj[j];

#pragma unroll
        for (int i = 0; i < 8; i++) {
            float rmax = sv[i][0];
#pragma unroll
            for (int j = 1; j < 4; j++) rmax = fmaxf(rmax, sv[i][j]);
#pragma unroll
            for (int off = 1; off < 16; off <<= 1)
                rmax = fmaxf(rmax, __shfl_xor_sync(0xffffffffu, rmax, off));
            float mnew = fmaxf(m[i], rmax);
            float fac = __expf(m[i] - mnew);
            float rsum = 0.0f;
#pragma unroll
            for (int j = 0; j < 4; j++) {
                float p = __expf(sv[i][j] - mnew);
                sv[i][j] = p;
                rsum += p;
            }
#pragma unroll
            for (int off = 1; off < 16; off <<= 1)
                rsum += __shfl_xor_sync(0xffffffffu, rsum, off);
            l[i] = l[i] * fac + rsum;
            m[i] = mnew;
#pragma unroll
            for (int j = 0; j < 4; j++) o[i][j] *= fac;
            *(float4*)&Ps[(ty * 8 + i) * 68 + tx * 4] =
                make_float4(sv[i][0], sv[i][1], sv[i][2], sv[i][3]);
        }
        __syncthreads();

#pragma unroll 4
        for (int kk2 = 0; kk2 < 64; kk2++) {
            float4 vv = *(const float4*)&Vs[kk2 * 68 + tx * 4];
            float vr[4] = {vv.x, vv.y, vv.z, vv.w};
#pragma unroll
            for (int i = 0; i < 8; i++) {
                float p = Ps[(ty * 8 + i) * 68 + kk2];
#pragma unroll
                for (int j = 0; j < 4; j++) o[i][j] += p * vr[j];
            }
        }
    }

#pragma unroll
    for (int i = 0; i < 8; i++) {
        float inv = 1.0f / l[i];
        float4 c = make_float4(o[i][0] * inv, o[i][1] * inv,
                               o[i][2] * inv, o[i][3] * inv);
        *(float4*)(ctx + base + (size_t)(q0 + ty * 8 + i) * HIDN + tx * 4) = c;
    }
}

// ---------------------------------------------------------------------------
extern "C" void kernel_launch(void* const* d_in, const int* in_sizes, int n_in,
                              void* d_out, int out_size)
{
    const float* hidden = (const float*)d_in[0];
    const float* Wq = (const float*)d_in[1];  const float* bq = (const float*)d_in[2];
    const float* Wk = (const float*)d_in[3];  const float* bk = (const float*)d_in[4];
    const float* Wv = (const float*)d_in[5];  const float* bv = (const float*)d_in[6];
    const float* Wo = (const float*)d_in[7];  const float* bo = (const float*)d_in[8];
    const float* Wpe = (const float*)d_in[9]; const float* bpe = (const float*)d_in[10];
    const float* pos_bias = (const float*)d_in[11];
    float* out = (float*)d_out;

    float *dq, *dk, *dv, *dctx;
    cudaGetSymbolAddress((void**)&dq, g_q);
    cudaGetSymbolAddress((void**)&dk, g_k);
    cudaGetSymbolAddress((void**)&dv, g_v);
    cudaGetSymbolAddress((void**)&dctx, g_ctx);
    __nv_bfloat16 *ae, *ce, *we;
    cudaGetSymbolAddress((void**)&ae, g_ae);
    cudaGetSymbolAddress((void**)&ce, g_ce);
    cudaGetSymbolAddress((void**)&we, g_we);
    __nv_bfloat16* weq = we;
    __nv_bfloat16* wek = we + (size_t)1 * HIDN * KE;
    __nv_bfloat16* wev = we + (size_t)2 * HIDN * KE;
    __nv_bfloat16* weo = we + (size_t)3 * HIDN * KE;

    const size_t ATTN_SMEM = (size_t)(64 * 128 + 64 * 64 + 64 * 68 + 128 * 68 + 64) * sizeof(float);
    cudaFuncSetAttribute(attn_kernel, cudaFuncAttributeMaxDynamicSharedMemorySize, (int)ATTN_SMEM);
    cudaFuncSetAttribute(gemm_tc, cudaFuncAttributeMaxDynamicSharedMemorySize, GEMM_SMEM);

    // convert weights + activations to hi/lo bf16 split
    prep_w<<<dim3(HIDN, 1, 4), 256>>>(Wq, Wk, Wv, Wo, weq, wek, wev, weo);
    prep_a<true><<<NTOK, 256>>>(hidden, Wpe, bpe, ae);

    // QKV projections on HMMA tensor cores
    gemm_tc<<<dim3(8, 128, 3), 256, GEMM_SMEM>>>(ae,
                                                 weq, bq, dq,
                                                 wek, bk, dk,
                                                 wev, bv, dv);
    // attention (fp32)
    attn_kernel<<<dim3(8, HH, BB), 256, ATTN_SMEM>>>(dq, dk, dv, pos_bias, dctx);

    // ctx -> split, then O projection
    prep_a<false><<<NTOK, 256>>>(dctx, nullptr, nullptr, ce);
    gemm_tc<<<dim3(8, 128, 1), 256, GEMM_SMEM>>>(ce,
                                                 weo, bo, out,
                                                 weo, bo, out,
                                                 weo, bo, out);
}

// round 4
// speedup vs baseline: 2.2971x; 1.4124x over previous
#include <cuda_runtime.h>
#include <cuda_bf16.h>
#include <cstdint>

#define HIDN 1024
#define BB 16
#define SS 1024
#define HH 16
#define DD 64
#define NTOK (BB*SS)
#define KE 2048   // [hi | lo] physical layout

// ---------------- scratch (__device__ globals, allocation-free rule) -------
__device__ float g_q[NTOK * HIDN];
__device__ float g_k[NTOK * HIDN];
__device__ float g_v[NTOK * HIDN];
__device__ float g_ctx[NTOK * HIDN];
__device__ __nv_bfloat16 g_ae[(size_t)NTOK * KE];
__device__ __nv_bfloat16 g_ce[(size_t)NTOK * KE];
__device__ __nv_bfloat16 g_we[4][(size_t)HIDN * KE];

// ---------------- helpers ---------------------------------------------------
__device__ __forceinline__ uint32_t smem_u32(const void* p) {
    uint32_t a;
    asm("{ .reg .u64 t; cvta.to.shared.u64 t, %1; cvt.u32.u64 %0, t; }" : "=r"(a) : "l"(p));
    return a;
}
__device__ __forceinline__ void ldsm_x4(uint32_t& r0, uint32_t& r1, uint32_t& r2,
                                        uint32_t& r3, uint32_t a) {
    asm volatile("ldmatrix.sync.aligned.m8n8.x4.shared.b16 {%0,%1,%2,%3}, [%4];"
                 : "=r"(r0), "=r"(r1), "=r"(r2), "=r"(r3) : "r"(a));
}
__device__ __forceinline__ void mma16816(float* c, const uint32_t* a, const uint32_t* b) {
    asm volatile("mma.sync.aligned.m16n8k16.row.col.f32.bf16.bf16.f32 "
                 "{%0,%1,%2,%3}, {%4,%5,%6,%7}, {%8,%9}, {%0,%1,%2,%3};"
                 : "+f"(c[0]), "+f"(c[1]), "+f"(c[2]), "+f"(c[3])
                 : "r"(a[0]), "r"(a[1]), "r"(a[2]), "r"(a[3]), "r"(b[0]), "r"(b[1]));
}
__device__ __forceinline__ void mma_tf32(float* c, const uint32_t* a, const uint32_t* b) {
    asm volatile("mma.sync.aligned.m16n8k8.row.col.f32.tf32.tf32.f32 "
                 "{%0,%1,%2,%3}, {%4,%5,%6,%7}, {%8,%9}, {%0,%1,%2,%3};"
                 : "+f"(c[0]), "+f"(c[1]), "+f"(c[2]), "+f"(c[3])
                 : "r"(a[0]), "r"(a[1]), "r"(a[2]), "r"(a[3]), "r"(b[0]), "r"(b[1]));
}
__device__ __forceinline__ uint32_t f2tf32(float x) {
    uint32_t r; asm("cvt.rna.tf32.f32 %0, %1;" : "=r"(r) : "f"(x)); return r;
}
// pack two floats into bf16x2: low half = lo, high half = hi
__device__ __forceinline__ uint32_t packbf(float lo, float hi) {
    uint32_t r; asm("cvt.rn.bf16x2.f32 %0, %1, %2;" : "=r"(r) : "f"(hi), "f"(lo)); return r;
}
__device__ __forceinline__ void split2(float x0, float x1, uint32_t& hi, uint32_t& lo) {
    __nv_bfloat16 h0 = __float2bfloat16_rn(x0), h1 = __float2bfloat16_rn(x1);
    __nv_bfloat162 hh; hh.x = h0; hh.y = h1;
    hi = *(uint32_t*)&hh;
    lo = packbf(x0 - __bfloat162float(h0), x1 - __bfloat162float(h1));
}

// ---------------------------------------------------------------------------
// Conversion kernels: fp32 -> [hi | lo] bf16 split (lo = x - bf16(x))
// ---------------------------------------------------------------------------
template<bool FUSE_POS>
__global__ void prep_a(const float* __restrict__ src, const float* __restrict__ wpe,
                       const float* __restrict__ bpe, __nv_bfloat16* __restrict__ E)
{
    int m = blockIdx.x;
    int k = threadIdx.x * 4;
    float4 v = *(const float4*)(src + (size_t)m * HIDN + k);
    if (FUSE_POS) {
        float posv = (float)((m & (SS - 1)) - SS / 2) * (1.0f / (512.0f + 1e-6f));
        float4 wp = *(const float4*)(wpe + k);
        float4 bp = *(const float4*)(bpe + k);
        v.x += posv * wp.x + bp.x;  v.y += posv * wp.y + bp.y;
        v.z += posv * wp.z + bp.z;  v.w += posv * wp.w + bp.w;
    }
    float a[4] = {v.x, v.y, v.z, v.w};
    __nv_bfloat16* hi = E + (size_t)m * KE + k;
    __nv_bfloat16* lo = hi + HIDN;
#pragma unroll
    for (int j = 0; j < 4; j++) {
        __nv_bfloat16 hb = __float2bfloat16(a[j]);
        hi[j] = hb;
        lo[j] = __float2bfloat16(a[j] - __bfloat162float(hb));
    }
}

__global__ void prep_w(const float* __restrict__ W0, const float* __restrict__ W1,
                       const float* __restrict__ W2, const float* __restrict__ W3,
                       __nv_bfloat16* __restrict__ E0, __nv_bfloat16* __restrict__ E1,
                       __nv_bfloat16* __restrict__ E2, __nv_bfloat16* __restrict__ E3)
{
    const float* W; __nv_bfloat16* E;
    switch (blockIdx.z) {
        case 0: W = W0; E = E0; break;
        case 1: W = W1; E = E1; break;
        case 2: W = W2; E = E2; break;
        default: W = W3; E = E3; break;
    }
    int n = blockIdx.x;
    int k = threadIdx.x * 4;
    float4 v = *(const float4*)(W + (size_t)n * HIDN + k);
    float a[4] = {v.x, v.y, v.z, v.w};
    __nv_bfloat16* hi = E + (size_t)n * KE + k;
    __nv_bfloat16* lo = hi + HIDN;
#pragma unroll
    for (int j = 0; j < 4; j++) {
        __nv_bfloat16 hb = __float2bfloat16(a[j]);
        hi[j] = hb;
        lo[j] = __float2bfloat16(a[j] - __bfloat162float(hb));
    }
}

// ---------------------------------------------------------------------------
// HMMA GEMM: C[M,1024] = Ae @ We^T + bias  (bf16 hi/lo split, fp32 accum)
// ---------------------------------------------------------------------------
#define LDA 72
#define T_AH 0
#define T_AL (128 * LDA)
#define T_WH (2 * 128 * LDA)
#define T_WL (3 * 128 * LDA)
#define GEMM_SMEM (4 * 128 * LDA * 2)

__global__ __launch_bounds__(256, 2)
void gemm_tc(const __nv_bfloat16* __restrict__ Ae,
             const __nv_bfloat16* __restrict__ W0e, const float* __restrict__ b0, float* __restrict__ C0,
             const __nv_bfloat16* __restrict__ W1e, const float* __restrict__ b1, float* __restrict__ C1,
             const __nv_bfloat16* __restrict__ W2e, const float* __restrict__ b2, float* __restrict__ C2)
{
    const __nv_bfloat16* We; const float* bias; float* C;
    if (blockIdx.z == 0)      { We = W0e; bias = b0; C = C0; }
    else if (blockIdx.z == 1) { We = W1e; bias = b1; C = C1; }
    else                      { We = W2e; bias = b2; C = C2; }

    extern __shared__ __align__(16) __nv_bfloat16 smg[];
    const uint32_t sb = smem_u32(smg);

    const int tid = threadIdx.x;
    const int lane = tid & 31;
    const int wid = tid >> 5;
    const int wm = wid & 1;
    const int wn = wid >> 1;
    const int m0 = blockIdx.y * 128;
    const int n0 = blockIdx.x * 128;

    const int lrow = tid >> 1;
    const int lhalf = (tid & 1) * 32;
    const __nv_bfloat16* arow = Ae + (size_t)(m0 + lrow) * KE;
    const __nv_bfloat16* wrow = We + (size_t)(n0 + lrow) * KE;
    __nv_bfloat16* sAh = smg + T_AH + lrow * LDA + lhalf;
    __nv_bfloat16* sAl = smg + T_AL + lrow * LDA + lhalf;
    __nv_bfloat16* sWh = smg + T_WH + lrow * LDA + lhalf;
    __nv_bfloat16* sWl = smg + T_WL + lrow * LDA + lhalf;

    const int aRow = (wm * 64 + (lane & 15)) * LDA + (lane >> 4) * 8;
    const int quad = lane >> 3;
    const int bRow = (wn * 32 + (quad >> 1) * 8 + (lane & 7)) * LDA + (quad & 1) * 8;

    float acc[4][4][4];
#pragma unroll
    for (int i = 0; i < 4; i++)
#pragma unroll
        for (int j = 0; j < 4; j++)
#pragma unroll
            for (int r = 0; r < 4; r++) acc[i][j][r] = 0.0f;

    for (int chunk = 0; chunk < 16; chunk++) {
        const int kb = chunk * 64;
        __syncthreads();
#pragma unroll
        for (int j = 0; j < 4; j++) {
            *(uint4*)(sAh + j * 8) = *(const uint4*)(arow + kb + lhalf + j * 8);
            *(uint4*)(sAl + j * 8) = *(const uint4*)(arow + HIDN + kb + lhalf + j * 8);
            *(uint4*)(sWh + j * 8) = *(const uint4*)(wrow + kb + lhalf + j * 8);
            *(uint4*)(sWl + j * 8) = *(const uint4*)(wrow + HIDN + kb + lhalf + j * 8);
        }
        __syncthreads();

#pragma unroll
        for (int ks = 0; ks < 4; ks++) {
            const int k0 = ks * 16;
            uint32_t aH[16];
#pragma unroll
            for (int fm = 0; fm < 4; fm++)
                ldsm_x4(aH[fm * 4 + 0], aH[fm * 4 + 1], aH[fm * 4 + 2], aH[fm * 4 + 3],
                        sb + 2 * (T_AH + aRow + fm * 16 * LDA + k0));
            {
                uint32_t bH[8];
#pragma unroll
                for (int fp = 0; fp < 2; fp++)
                    ldsm_x4(bH[fp * 4 + 0], bH[fp * 4 + 1], bH[fp * 4 + 2], bH[fp * 4 + 3],
                            sb + 2 * (T_WH + bRow + fp * 16 * LDA + k0));
#pragma unroll
                for (int fm = 0; fm < 4; fm++)
#pragma unroll
                    for (int fn = 0; fn < 4; fn++)
                        mma16816(acc[fm][fn], &aH[fm * 4], &bH[fn * 2]);
                {
                    uint32_t aL[16];
#pragma unroll
                    for (int fm = 0; fm < 4; fm++)
                        ldsm_x4(aL[fm * 4 + 0], aL[fm * 4 + 1], aL[fm * 4 + 2], aL[fm * 4 + 3],
                                sb + 2 * (T_AL + aRow + fm * 16 * LDA + k0));
#pragma unroll
                    for (int fm = 0; fm < 4; fm++)
#pragma unroll
                        for (int fn = 0; fn < 4; fn++)
                            mma16816(acc[fm][fn], &aL[fm * 4], &bH[fn * 2]);
                }
            }
            {
                uint32_t bL[8];
#pragma unroll
                for (int fp = 0; fp < 2; fp++)
                    ldsm_x4(bL[fp * 4 + 0], bL[fp * 4 + 1], bL[fp * 4 + 2], bL[fp * 4 + 3],
                            sb + 2 * (T_WL + bRow + fp * 16 * LDA + k0));
#pragma unroll
                for (int fm = 0; fm < 4; fm++)
#pragma unroll
                    for (int fn = 0; fn < 4; fn++)
                        mma16816(acc[fm][fn], &aH[fm * 4], &bL[fn * 2]);
            }
        }
    }

    const int rt = lane >> 2;
    const int ct = (lane & 3) * 2;
#pragma unroll
    for (int fn = 0; fn < 4; fn++) {
        const int gcol = n0 + wn * 32 + fn * 8 + ct;
        const float bn0 = __ldg(bias + gcol);
        const float bn1 = __ldg(bias + gcol + 1);
#pragma unroll
        for (int fm = 0; fm < 4; fm++) {
            const int grow = m0 + wm * 64 + fm * 16 + rt;
            float2 v0 = make_float2(acc[fm][fn][0] + bn0, acc[fm][fn][1] + bn1);
            float2 v1 = make_float2(acc[fm][fn][2] + bn0, acc[fm][fn][3] + bn1);
            *(float2*)(C + (size_t)grow * HIDN + gcol) = v0;
            *(float2*)(C + (size_t)(grow + 8) * HIDN + gcol) = v1;
        }
    }
}

// ---------------------------------------------------------------------------
// Tensor-core flash attention.
// QK^T in tf32 (m16n8k8); PV in bf16 hi/lo 3-pass (m16n8k16).
// CTA = 128 q-rows for one (b,h); 8 warps x 16 rows; BK = 64.
// smem bytes: Q[128][68]u32 | K[64][68]u32 | Vh[64][72]bf16 | Vl | bias[64]f32
// ---------------------------------------------------------------------------
#define AQ_OFF 0
#define AK_OFF 34816
#define AVH_OFF 52224
#define AVL_OFF 61440
#define ABS_OFF 70656
#define ATTN_SMEM 70912

__global__ __launch_bounds__(256, 2)
void attn_tc(const float* __restrict__ Q, const float* __restrict__ K,
             const float* __restrict__ V, const float* __restrict__ pos_bias,
             float* __restrict__ ctx)
{
    extern __shared__ __align__(16) char sma[];
    uint32_t* sQ = (uint32_t*)(sma + AQ_OFF);           // [128][68] tf32
    uint32_t* sK = (uint32_t*)(sma + AK_OFF);           // [64][68]  tf32
    __nv_bfloat16* sVh = (__nv_bfloat16*)(sma + AVH_OFF); // [d=64][key=72pad]
    __nv_bfloat16* sVl = (__nv_bfloat16*)(sma + AVL_OFF);
    float* sB = (float*)(sma + ABS_OFF);                // [64]

    const int tid = threadIdx.x;
    const int lane = tid & 31;
    const int w = tid >> 5;
    const int lr = lane >> 2;     // 0..7
    const int lc = lane & 3;      // 0..3
    const int q0 = blockIdx.x * 128;
    const int h = blockIdx.y, b = blockIdx.z;
    const size_t base = ((size_t)b * SS) * HIDN + h * DD;

    // ---- Q tile fill (scaled 1/8, tf32-converted) ----
#pragma unroll
    for (int i = 0; i < 8; i++) {
        int f = tid + 256 * i;          // 0..2047
        int row = f >> 4;
        int c4 = (f & 15) * 4;
        float4 q = *(const float4*)(Q + base + (size_t)(q0 + row) * HIDN + c4);
        uint4 t;
        t.x = f2tf32(q.x * 0.125f); t.y = f2tf32(q.y * 0.125f);
        t.z = f2tf32(q.z * 0.125f); t.w = f2tf32(q.w * 0.125f);
        *(uint4*)(sQ + row * 68 + c4) = t;
    }

    float m0v = -1e30f, m1v = -1e30f, l0v = 0.0f, l1v = 0.0f;
    float o[8][4];
#pragma unroll
    for (int j = 0; j < 8; j++)
#pragma unroll
        for (int r = 0; r < 4; r++) o[j][r] = 0.0f;

    const uint32_t* qrow = sQ + (w * 16 + lr) * 68 + lc;

    for (int kt0 = 0; kt0 < SS; kt0 += 64) {
        __syncthreads();
        // ---- K (tf32) + V (bf16 hi/lo transposed) fill ----
#pragma unroll
        for (int i = 0; i < 4; i++) {
            int f = tid + 256 * i;      // 0..1023
            int row = f >> 4;           // key 0..63
            int c4 = (f & 15) * 4;      // d
            float4 kv = *(const float4*)(K + base + (size_t)(kt0 + row) * HIDN + c4);
            uint4 t;
            t.x = f2tf32(kv.x); t.y = f2tf32(kv.y);
            t.z = f2tf32(kv.z); t.w = f2tf32(kv.w);
            *(uint4*)(sK + row * 68 + c4) = t;
            float4 vv = *(const float4*)(V + base + (size_t)(kt0 + row) * HIDN + c4);
            float vals[4] = {vv.x, vv.y, vv.z, vv.w};
#pragma unroll
            for (int e = 0; e < 4; e++) {
                __nv_bfloat16 hb = __float2bfloat16_rn(vals[e]);
                sVh[(c4 + e) * 72 + row] = hb;
                sVl[(c4 + e) * 72 + row] = __float2bfloat16_rn(vals[e] - __bfloat162float(hb));
            }
        }
        if (tid < 64) sB[tid] = pos_bias[h * 1025 + kt0 + tid];
        __syncthreads();

        // ---- S = Q K^T (tf32 mma) ----
        float s[8][4];
#pragma unroll
        for (int j = 0; j < 8; j++)
#pragma unroll
            for (int r = 0; r < 4; r++) s[j][r] = 0.0f;

#pragma unroll
        for (int ks = 0; ks < 8; ks++) {
            const int k0 = ks * 8;
            uint32_t a[4];
            a[0] = qrow[k0];           a[1] = qrow[k0 + 8 * 68];
            a[2] = qrow[k0 + 4];       a[3] = qrow[k0 + 8 * 68 + 4];
#pragma unroll
            for (int j = 0; j < 8; j++) {
                const uint32_t* kb = sK + (j * 8 + lr) * 68 + lc + k0;
                uint32_t bfr[2] = { kb[0], kb[4] };
                mma_tf32(s[j], a, bfr);
            }
        }

        // ---- bias + online softmax ----
        float rmax0 = -1e30f, rmax1 = -1e30f;
#pragma unroll
        for (int j = 0; j < 8; j++) {
            float b0 = sB[j * 8 + 2 * lc], b1 = sB[j * 8 + 2 * lc + 1];
            s[j][0] += b0; s[j][1] += b1; s[j][2] += b0; s[j][3] += b1;
            rmax0 = fmaxf(rmax0, fmaxf(s[j][0], s[j][1]));
            rmax1 = fmaxf(rmax1, fmaxf(s[j][2], s[j][3]));
        }
        rmax0 = fmaxf(rmax0, __shfl_xor_sync(0xffffffffu, rmax0, 1));
        rmax0 = fmaxf(rmax0, __shfl_xor_sync(0xffffffffu, rmax0, 2));
        rmax1 = fmaxf(rmax1, __shfl_xor_sync(0xffffffffu, rmax1, 1));
        rmax1 = fmaxf(rmax1, __shfl_xor_sync(0xffffffffu, rmax1, 2));
        float mn0 = fmaxf(m0v, rmax0), mn1 = fmaxf(m1v, rmax1);
        float fac0 = __expf(m0v - mn0), fac1 = __expf(m1v - mn1);
        float rs0 = 0.0f, rs1 = 0.0f;
#pragma unroll
        for (int j = 0; j < 8; j++) {
            s[j][0] = __expf(s[j][0] - mn0); s[j][1] = __expf(s[j][1] - mn0);
            s[j][2] = __expf(s[j][2] - mn1); s[j][3] = __expf(s[j][3] - mn1);
            rs0 += s[j][0] + s[j][1];
            rs1 += s[j][2] + s[j][3];
        }
        rs0 += __shfl_xor_sync(0xffffffffu, rs0, 1);
        rs0 += __shfl_xor_sync(0xffffffffu, rs0, 2);
        rs1 += __shfl_xor_sync(0xffffffffu, rs1, 1);
        rs1 += __shfl_xor_sync(0xffffffffu, rs1, 2);
        l0v = l0v * fac0 + rs0;  m0v = mn0;
        l1v = l1v * fac1 + rs1;  m1v = mn1;
#pragma unroll
        for (int j = 0; j < 8; j++) {
            o[j][0] *= fac0; o[j][1] *= fac0;
            o[j][2] *= fac1; o[j][3] *= fac1;
        }

        // ---- P -> bf16 hi/lo A-fragments (D-frag layout == A-frag layout) ----
        uint32_t ph[4][4], pl[4][4];
#pragma unroll
        for (int kc = 0; kc < 4; kc++) {
            const int j0 = 2 * kc, j1 = 2 * kc + 1;
            split2(s[j0][0], s[j0][1], ph[kc][0], pl[kc][0]);
            split2(s[j0][2], s[j0][3], ph[kc][1], pl[kc][1]);
            split2(s[j1][0], s[j1][1], ph[kc][2], pl[kc][2]);
            split2(s[j1][2], s[j1][3], ph[kc][3], pl[kc][3]);
        }

        // ---- O += P V (bf16 3-pass) ----
#pragma unroll
        for (int j = 0; j < 8; j++) {
            const __nv_bfloat16* vbh = sVh + (j * 8 + lr) * 72 + 2 * lc;
            const __nv_bfloat16* vbl = sVl + (j * 8 + lr) * 72 + 2 * lc;
#pragma unroll
            for (int kc = 0; kc < 4; kc++) {
                uint32_t bh[2] = { *(const uint32_t*)(vbh + kc * 16),
                                   *(const uint32_t*)(vbh + kc * 16 + 8) };
                uint32_t bl[2] = { *(const uint32_t*)(vbl + kc * 16),
                                   *(const uint32_t*)(vbl + kc * 16 + 8) };
                mma16816(o[j], ph[kc], bh);
                mma16816(o[j], pl[kc], bh);
                mma16816(o[j], ph[kc], bl);
            }
        }
    }

    // ---- epilogue ----
    const float inv0 = 1.0f / l0v, inv1 = 1.0f / l1v;
    const int row0 = q0 + w * 16 + lr;
#pragma unroll
    for (int j = 0; j < 8; j++) {
        const int col = j * 8 + 2 * lc;
        *(float2*)(ctx + base + (size_t)row0 * HIDN + col) =
            make_float2(o[j][0] * inv0, o[j][1] * inv0);
        *(float2*)(ctx + base + (size_t)(row0 + 8) * HIDN + col) =
            make_float2(o[j][2] * inv1, o[j][3] * inv1);
    }
}

// ---------------------------------------------------------------------------
extern "C" void kernel_launch(void* const* d_in, const int* in_sizes, int n_in,
                              void* d_out, int out_size)
{
    const float* hidden = (const float*)d_in[0];
    const float* Wq = (const float*)d_in[1];  const float* bq = (const float*)d_in[2];
    const float* Wk = (const float*)d_in[3];  const float* bk = (const float*)d_in[4];
    const float* Wv = (const float*)d_in[5];  const float* bv = (const float*)d_in[6];
    const float* Wo = (const float*)d_in[7];  const float* bo = (const float*)d_in[8];
    const float* Wpe = (const float*)d_in[9]; const float* bpe = (const float*)d_in[10];
    const float* pos_bias = (const float*)d_in[11];
    float* out = (float*)d_out;

    float *dq, *dk, *dv, *dctx;
    cudaGetSymbolAddress((void**)&dq, g_q);
    cudaGetSymbolAddress((void**)&dk, g_k);
    cudaGetSymbolAddress((void**)&dv, g_v);
    cudaGetSymbolAddress((void**)&dctx, g_ctx);
    __nv_bfloat16 *ae, *ce, *we;
    cudaGetSymbolAddress((void**)&ae, g_ae);
    cudaGetSymbolAddress((void**)&ce, g_ce);
    cudaGetSymbolAddress((void**)&we, g_we);
    __nv_bfloat16* weq = we;
    __nv_bfloat16* wek = we + (size_t)1 * HIDN * KE;
    __nv_bfloat16* wev = we + (size_t)2 * HIDN * KE;
    __nv_bfloat16* weo = we + (size_t)3 * HIDN * KE;

    cudaFuncSetAttribute(attn_tc, cudaFuncAttributeMaxDynamicSharedMemorySize, ATTN_SMEM);
    cudaFuncSetAttribute(gemm_tc, cudaFuncAttributeMaxDynamicSharedMemorySize, GEMM_SMEM);

    // convert weights + activations to hi/lo bf16 split
    prep_w<<<dim3(HIDN, 1, 4), 256>>>(Wq, Wk, Wv, Wo, weq, wek, wev, weo);
    prep_a<true><<<NTOK, 256>>>(hidden, Wpe, bpe, ae);

    // QKV projections on HMMA tensor cores
    gemm_tc<<<dim3(8, 128, 3), 256, GEMM_SMEM>>>(ae,
                                                 weq, bq, dq,
                                                 wek, bk, dk,
                                                 wev, bv, dv);
    // tensor-core attention
    attn_tc<<<dim3(8, HH, BB), 256, ATTN_SMEM>>>(dq, dk, dv, pos_bias, dctx);

    // ctx -> split, then O projection
    prep_a<false><<<NTOK, 256>>>(dctx, nullptr, nullptr, ce);
    gemm_tc<<<dim3(8, 128, 1), 256, GEMM_SMEM>>>(ce,
                                                 weo, bo, out,
                                                 weo, bo, out,
                                                 weo, bo, out);
}

// round 5
// speedup vs baseline: 2.5746x; 1.1208x over previous
#include <cuda_runtime.h>
#include <cuda_bf16.h>
#include <cstdint>

#define HIDN 1024
#define BB 16
#define SS 1024
#define HH 16
#define DD 64
#define NTOK (BB*SS)
#define KE 2048   // [hi | lo] physical layout

// ---------------- scratch (__device__ globals, allocation-free rule) -------
__device__ float g_q[NTOK * HIDN];
__device__ float g_k[NTOK * HIDN];
__device__ float g_v[NTOK * HIDN];
__device__ float g_ctx[NTOK * HIDN];
__device__ __nv_bfloat16 g_ae[(size_t)NTOK * KE];
__device__ __nv_bfloat16 g_ce[(size_t)NTOK * KE];
__device__ __nv_bfloat16 g_we[4][(size_t)HIDN * KE];

// ---------------- helpers ---------------------------------------------------
__device__ __forceinline__ uint32_t smem_u32(const void* p) {
    uint32_t a;
    asm("{ .reg .u64 t; cvta.to.shared.u64 t, %1; cvt.u32.u64 %0, t; }" : "=r"(a) : "l"(p));
    return a;
}
__device__ __forceinline__ void ldsm_x4(uint32_t& r0, uint32_t& r1, uint32_t& r2,
                                        uint32_t& r3, uint32_t a) {
    asm volatile("ldmatrix.sync.aligned.m8n8.x4.shared.b16 {%0,%1,%2,%3}, [%4];"
                 : "=r"(r0), "=r"(r1), "=r"(r2), "=r"(r3) : "r"(a));
}
__device__ __forceinline__ void mma16816(float* c, const uint32_t* a, const uint32_t* b) {
    asm volatile("mma.sync.aligned.m16n8k16.row.col.f32.bf16.bf16.f32 "
                 "{%0,%1,%2,%3}, {%4,%5,%6,%7}, {%8,%9}, {%0,%1,%2,%3};"
                 : "+f"(c[0]), "+f"(c[1]), "+f"(c[2]), "+f"(c[3])
                 : "r"(a[0]), "r"(a[1]), "r"(a[2]), "r"(a[3]), "r"(b[0]), "r"(b[1]));
}
__device__ __forceinline__ void mma_tf32(float* c, const uint32_t* a, const uint32_t* b) {
    asm volatile("mma.sync.aligned.m16n8k8.row.col.f32.tf32.tf32.f32 "
                 "{%0,%1,%2,%3}, {%4,%5,%6,%7}, {%8,%9}, {%0,%1,%2,%3};"
                 : "+f"(c[0]), "+f"(c[1]), "+f"(c[2]), "+f"(c[3])
                 : "r"(a[0]), "r"(a[1]), "r"(a[2]), "r"(a[3]), "r"(b[0]), "r"(b[1]));
}
__device__ __forceinline__ uint32_t f2tf32(float x) {
    uint32_t r; asm("cvt.rna.tf32.f32 %0, %1;" : "=r"(r) : "f"(x)); return r;
}
__device__ __forceinline__ uint32_t packbf(float lo, float hi) {
    uint32_t r; asm("cvt.rn.bf16x2.f32 %0, %1, %2;" : "=r"(r) : "f"(hi), "f"(lo)); return r;
}
// pack (x0 -> low half, x1 -> high half) hi/lo split
__device__ __forceinline__ void split2(float x0, float x1, uint32_t& hi, uint32_t& lo) {
    __nv_bfloat16 h0 = __float2bfloat16_rn(x0), h1 = __float2bfloat16_rn(x1);
    __nv_bfloat162 hh; hh.x = h0; hh.y = h1;
    hi = *(uint32_t*)&hh;
    lo = packbf(x0 - __bfloat162float(h0), x1 - __bfloat162float(h1));
}
__device__ __forceinline__ void cp16(uint32_t dst, const void* src) {
    asm volatile("cp.async.cg.shared.global [%0], [%1], 16;" :: "r"(dst), "l"(src));
}
#define CP_COMMIT() asm volatile("cp.async.commit_group;" ::: "memory")
#define CP_WAIT(n)  asm volatile("cp.async.wait_group %0;" :: "n"(n) : "memory")

// ---------------------------------------------------------------------------
// Conversion kernels: fp32 -> [hi | lo] bf16 split (lo = x - bf16(x))
// ---------------------------------------------------------------------------
template<bool FUSE_POS>
__global__ void prep_a(const float* __restrict__ src, const float* __restrict__ wpe,
                       const float* __restrict__ bpe, __nv_bfloat16* __restrict__ E)
{
    int m = blockIdx.x;
    int k = threadIdx.x * 4;
    float4 v = *(const float4*)(src + (size_t)m * HIDN + k);
    if (FUSE_POS) {
        float posv = (float)((m & (SS - 1)) - SS / 2) * (1.0f / (512.0f + 1e-6f));
        float4 wp = *(const float4*)(wpe + k);
        float4 bp = *(const float4*)(bpe + k);
        v.x += posv * wp.x + bp.x;  v.y += posv * wp.y + bp.y;
        v.z += posv * wp.z + bp.z;  v.w += posv * wp.w + bp.w;
    }
    float a[4] = {v.x, v.y, v.z, v.w};
    __nv_bfloat16* hi = E + (size_t)m * KE + k;
    __nv_bfloat16* lo = hi + HIDN;
#pragma unroll
    for (int j = 0; j < 4; j++) {
        __nv_bfloat16 hb = __float2bfloat16(a[j]);
        hi[j] = hb;
        lo[j] = __float2bfloat16(a[j] - __bfloat162float(hb));
    }
}

__global__ void prep_w(const float* __restrict__ W0, const float* __restrict__ W1,
                       const float* __restrict__ W2, const float* __restrict__ W3,
                       __nv_bfloat16* __restrict__ E0, __nv_bfloat16* __restrict__ E1,
                       __nv_bfloat16* __restrict__ E2, __nv_bfloat16* __restrict__ E3)
{
    const float* W; __nv_bfloat16* E;
    switch (blockIdx.z) {
        case 0: W = W0; E = E0; break;
        case 1: W = W1; E = E1; break;
        case 2: W = W2; E = E2; break;
        default: W = W3; E = E3; break;
    }
    int n = blockIdx.x;
    int k = threadIdx.x * 4;
    float4 v = *(const float4*)(W + (size_t)n * HIDN + k);
    float a[4] = {v.x, v.y, v.z, v.w};
    __nv_bfloat16* hi = E + (size_t)n * KE + k;
    __nv_bfloat16* lo = hi + HIDN;
#pragma unroll
    for (int j = 0; j < 4; j++) {
        __nv_bfloat16 hb = __float2bfloat16(a[j]);
        hi[j] = hb;
        lo[j] = __float2bfloat16(a[j] - __bfloat162float(hb));
    }
}

// ---------------------------------------------------------------------------
// HMMA GEMM, cp.async double-buffered. C = Ae @ We^T + bias.
// CTA 128x128, 256 thr (warp grid 2x4 -> 64x32/warp), K-chunk 32, 2 stages.
// 3 mma passes per chunk: Ah*Wh + Al*Wh + Ah*Wl.
// ---------------------------------------------------------------------------
#define CH 32
#define LDA 40                       // 32 + 8 pad (elements)
#define TILE_EL (128 * LDA)          // 5120
#define STAGE_EL (4 * TILE_EL)       // 20480 elements
#define STAGE_B  (STAGE_EL * 2)      // 40960 bytes
#define T_AH_EL 0
#define T_AL_EL TILE_EL
#define T_WH_EL (2 * TILE_EL)
#define T_WL_EL (3 * TILE_EL)
#define GEMM_SMEM (2 * STAGE_B)      // 81920 bytes
#define NCHUNK (HIDN / CH)           // 32

__global__ __launch_bounds__(256, 2)
void gemm_tc(const __nv_bfloat16* __restrict__ Ae,
             const __nv_bfloat16* __restrict__ W0e, const float* __restrict__ b0, float* __restrict__ C0,
             const __nv_bfloat16* __restrict__ W1e, const float* __restrict__ b1, float* __restrict__ C1,
             const __nv_bfloat16* __restrict__ W2e, const float* __restrict__ b2, float* __restrict__ C2)
{
    const __nv_bfloat16* We; const float* bias; float* C;
    if (blockIdx.z == 0)      { We = W0e; bias = b0; C = C0; }
    else if (blockIdx.z == 1) { We = W1e; bias = b1; C = C1; }
    else                      { We = W2e; bias = b2; C = C2; }

    extern __shared__ __align__(16) __nv_bfloat16 smg[];
    const uint32_t sb = smem_u32(smg);

    const int tid = threadIdx.x;
    const int lane = tid & 31;
    const int wid = tid >> 5;
    const int wm = wid & 1;
    const int wn = wid >> 1;
    const int m0 = blockIdx.y * 128;
    const int n0 = blockIdx.x * 128;

    // loader: row = tid>>1, 16-element half = (tid&1)*16
    const int lrow = tid >> 1;
    const int lh = (tid & 1) * 16;
    const __nv_bfloat16* arow = Ae + (size_t)(m0 + lrow) * KE;
    const __nv_bfloat16* wrow = We + (size_t)(n0 + lrow) * KE;
    const uint32_t dbase = sb + (uint32_t)(lrow * LDA + lh) * 2;

    const int aRow = (wm * 64 + (lane & 15)) * LDA + (lane >> 4) * 8;
    const int quad = lane >> 3;
    const int bRow = (wn * 32 + (quad >> 1) * 8 + (lane & 7)) * LDA + (quad & 1) * 8;

    float acc[4][4][4];
#pragma unroll
    for (int i = 0; i < 4; i++)
#pragma unroll
        for (int j = 0; j < 4; j++)
#pragma unroll
            for (int r = 0; r < 4; r++) acc[i][j][r] = 0.0f;

#define GEMM_ISSUE(chunk) do {                                                  \
    const int _kb = (chunk) * CH;                                               \
    const uint32_t _d = dbase + ((chunk) & 1) * STAGE_B;                        \
    cp16(_d + T_AH_EL * 2,      arow + _kb + lh);                               \
    cp16(_d + T_AH_EL * 2 + 16, arow + _kb + lh + 8);                           \
    cp16(_d + T_AL_EL * 2,      arow + HIDN + _kb + lh);                        \
    cp16(_d + T_AL_EL * 2 + 16, arow + HIDN + _kb + lh + 8);                    \
    cp16(_d + T_WH_EL * 2,      wrow + _kb + lh);                               \
    cp16(_d + T_WH_EL * 2 + 16, wrow + _kb + lh + 8);                           \
    cp16(_d + T_WL_EL * 2,      wrow + HIDN + _kb + lh);                        \
    cp16(_d + T_WL_EL * 2 + 16, wrow + HIDN + _kb + lh + 8);                    \
} while (0)

    GEMM_ISSUE(0); CP_COMMIT();

    for (int ch = 0; ch < NCHUNK; ch++) {
        if (ch + 1 < NCHUNK) { GEMM_ISSUE(ch + 1); CP_COMMIT(); CP_WAIT(1); }
        else                 { CP_WAIT(0); }
        __syncthreads();

        const uint32_t st = sb + (ch & 1) * STAGE_B;
#pragma unroll
        for (int ks = 0; ks < 2; ks++) {
            const int k0 = ks * 16;
            uint32_t aH[16];
#pragma unroll
            for (int fm = 0; fm < 4; fm++)
                ldsm_x4(aH[fm * 4 + 0], aH[fm * 4 + 1], aH[fm * 4 + 2], aH[fm * 4 + 3],
                        st + 2 * (T_AH_EL + aRow + fm * 16 * LDA + k0));
            {
                uint32_t bH[8];
#pragma unroll
                for (int fp = 0; fp < 2; fp++)
                    ldsm_x4(bH[fp * 4 + 0], bH[fp * 4 + 1], bH[fp * 4 + 2], bH[fp * 4 + 3],
                            st + 2 * (T_WH_EL + bRow + fp * 16 * LDA + k0));
#pragma unroll
                for (int fm = 0; fm < 4; fm++)
#pragma unroll
                    for (int fn = 0; fn < 4; fn++)
                        mma16816(acc[fm][fn], &aH[fm * 4], &bH[fn * 2]);
                {
                    uint32_t aL[16];
#pragma unroll
                    for (int fm = 0; fm < 4; fm++)
                        ldsm_x4(aL[fm * 4 + 0], aL[fm * 4 + 1], aL[fm * 4 + 2], aL[fm * 4 + 3],
                                st + 2 * (T_AL_EL + aRow + fm * 16 * LDA + k0));
#pragma unroll
                    for (int fm = 0; fm < 4; fm++)
#pragma unroll
                        for (int fn = 0; fn < 4; fn++)
                            mma16816(acc[fm][fn], &aL[fm * 4], &bH[fn * 2]);
                }
            }
            {
                uint32_t bL[8];
#pragma unroll
                for (int fp = 0; fp < 2; fp++)
                    ldsm_x4(bL[fp * 4 + 0], bL[fp * 4 + 1], bL[fp * 4 + 2], bL[fp * 4 + 3],
                            st + 2 * (T_WL_EL + bRow + fp * 16 * LDA + k0));
#pragma unroll
                for (int fm = 0; fm < 4; fm++)
#pragma unroll
                    for (int fn = 0; fn < 4; fn++)
                        mma16816(acc[fm][fn], &aH[fm * 4], &bL[fn * 2]);
            }
        }
        __syncthreads();
    }

    const int rt = lane >> 2;
    const int ct = (lane & 3) * 2;
#pragma unroll
    for (int fn = 0; fn < 4; fn++) {
        const int gcol = n0 + wn * 32 + fn * 8 + ct;
        const float bn0 = __ldg(bias + gcol);
        const float bn1 = __ldg(bias + gcol + 1);
#pragma unroll
        for (int fm = 0; fm < 4; fm++) {
            const int grow = m0 + wm * 64 + fm * 16 + rt;
            float2 v0 = make_float2(acc[fm][fn][0] + bn0, acc[fm][fn][1] + bn1);
            float2 v1 = make_float2(acc[fm][fn][2] + bn0, acc[fm][fn][3] + bn1);
            *(float2*)(C + (size_t)grow * HIDN + gcol) = v0;
            *(float2*)(C + (size_t)(grow + 8) * HIDN + gcol) = v1;
        }
    }
}

// ---------------------------------------------------------------------------
// Tensor-core flash attention, v2.
// 128 threads (4 warps), each warp owns 32 q-rows = two m16 tiles.
// K/V fragments are loaded once per warp and reused across both q-tiles.
// V fill packs key-pairs into bf16x2 words -> conflict-free stores.
// QK^T tf32; PV bf16 hi/lo 3-pass.
// ---------------------------------------------------------------------------
#define AQ_OFF 0
#define AK_OFF 34816
#define AVH_OFF 52224
#define AVL_OFF 61440
#define ABS_OFF 70656
#define ATTN_SMEM 70912

__global__ __launch_bounds__(128)
void attn_tc(const float* __restrict__ Q, const float* __restrict__ K,
             const float* __restrict__ V, const float* __restrict__ pos_bias,
             float* __restrict__ ctx)
{
    extern __shared__ __align__(16) char sma[];
    uint32_t* sQ = (uint32_t*)(sma + AQ_OFF);            // [128][68] tf32
    uint32_t* sK = (uint32_t*)(sma + AK_OFF);            // [64][68]  tf32
    uint32_t* sVh = (uint32_t*)(sma + AVH_OFF);          // [d=64][kp=36pad] bf16x2 key-pairs
    uint32_t* sVl = (uint32_t*)(sma + AVL_OFF);
    float* sB = (float*)(sma + ABS_OFF);                 // [64]

    const int tid = threadIdx.x;
    const int lane = tid & 31;
    const int w = tid >> 5;       // 0..3
    const int lr = lane >> 2;     // 0..7
    const int lc = lane & 3;      // 0..3
    const int q0 = blockIdx.x * 128;
    const int h = blockIdx.y, b = blockIdx.z;
    const size_t base = ((size_t)b * SS) * HIDN + h * DD;

    // ---- Q tile fill (scaled 1/8, tf32) ----
#pragma unroll
    for (int i = 0; i < 16; i++) {
        int f = tid + 128 * i;          // 0..2047
        int row = f >> 4;
        int c4 = (f & 15) * 4;
        float4 q = *(const float4*)(Q + base + (size_t)(q0 + row) * HIDN + c4);
        uint4 t;
        t.x = f2tf32(q.x * 0.125f); t.y = f2tf32(q.y * 0.125f);
        t.z = f2tf32(q.z * 0.125f); t.w = f2tf32(q.w * 0.125f);
        *(uint4*)(sQ + row * 68 + c4) = t;
    }

    // per-tile softmax state: tile0 rows (lr, lr+8), tile1 rows (+16)
    float m0a = -1e30f, m0b = -1e30f, l0a = 0.0f, l0b = 0.0f;
    float m1a = -1e30f, m1b = -1e30f, l1a = 0.0f, l1b = 0.0f;
    float o0[8][4], o1[8][4];
#pragma unroll
    for (int j = 0; j < 8; j++)
#pragma unroll
        for (int r = 0; r < 4; r++) { o0[j][r] = 0.0f; o1[j][r] = 0.0f; }

    const uint32_t* qrow0 = sQ + (w * 32 + lr) * 68 + lc;
    const uint32_t* qrow1 = qrow0 + 16 * 68;

    for (int kt0 = 0; kt0 < SS; kt0 += 64) {
        __syncthreads();
        // ---- K fill (tf32) ----
#pragma unroll
        for (int i = 0; i < 8; i++) {
            int f = tid + 128 * i;      // 0..1023
            int row = f >> 4;
            int c4 = (f & 15) * 4;
            float4 kv = *(const float4*)(K + base + (size_t)(kt0 + row) * HIDN + c4);
            uint4 t;
            t.x = f2tf32(kv.x); t.y = f2tf32(kv.y);
            t.z = f2tf32(kv.z); t.w = f2tf32(kv.w);
            *(uint4*)(sK + row * 68 + c4) = t;
        }
        // ---- V fill: key-pair packed, conflict-free ----
#pragma unroll
        for (int i = 0; i < 4; i++) {
            int u = tid + 128 * i;      // 0..511
            int kp = u & 31;            // key pair 0..31
            int d4 = u >> 5;            // 0..15
            const float* v0p = V + base + (size_t)(kt0 + 2 * kp) * HIDN + d4 * 4;
            float4 va = *(const float4*)v0p;
            float4 vb = *(const float4*)(v0p + HIDN);
            float a0[4] = {va.x, va.y, va.z, va.w};
            float a1[4] = {vb.x, vb.y, vb.z, vb.w};
#pragma unroll
            for (int e = 0; e < 4; e++) {
                uint32_t hw, lw;
                split2(a0[e], a1[e], hw, lw);       // key even -> low half
                sVh[(d4 * 4 + e) * 36 + kp] = hw;
                sVl[(d4 * 4 + e) * 36 + kp] = lw;
            }
        }
        if (tid < 64) sB[tid] = pos_bias[h * 1025 + kt0 + tid];
        __syncthreads();

        // ---- S = Q K^T for both q-tiles, K fragments shared ----
        float s0[8][4], s1[8][4];
#pragma unroll
        for (int j = 0; j < 8; j++)
#pragma unroll
            for (int r = 0; r < 4; r++) { s0[j][r] = 0.0f; s1[j][r] = 0.0f; }

#pragma unroll
        for (int ks = 0; ks < 8; ks++) {
            const int k0 = ks * 8;
            uint32_t a0[4], a1[4];
            a0[0] = qrow0[k0];         a0[1] = qrow0[k0 + 8 * 68];
            a0[2] = qrow0[k0 + 4];     a0[3] = qrow0[k0 + 8 * 68 + 4];
            a1[0] = qrow1[k0];         a1[1] = qrow1[k0 + 8 * 68];
            a1[2] = qrow1[k0 + 4];     a1[3] = qrow1[k0 + 8 * 68 + 4];
#pragma unroll
            for (int j = 0; j < 8; j++) {
                const uint32_t* kb = sK + (j * 8 + lr) * 68 + lc + k0;
                uint32_t bfr[2] = { kb[0], kb[4] };
                mma_tf32(s0[j], a0, bfr);
                mma_tf32(s1[j], a1, bfr);
            }
        }

        // ---- bias + online softmax, tile 0 ----
        {
            float rmax0 = -1e30f, rmax1 = -1e30f;
#pragma unroll
            for (int j = 0; j < 8; j++) {
                float bb0 = sB[j * 8 + 2 * lc], bb1 = sB[j * 8 + 2 * lc + 1];
                s0[j][0] += bb0; s0[j][1] += bb1; s0[j][2] += bb0; s0[j][3] += bb1;
                rmax0 = fmaxf(rmax0, fmaxf(s0[j][0], s0[j][1]));
                rmax1 = fmaxf(rmax1, fmaxf(s0[j][2], s0[j][3]));
            }
            rmax0 = fmaxf(rmax0, __shfl_xor_sync(0xffffffffu, rmax0, 1));
            rmax0 = fmaxf(rmax0, __shfl_xor_sync(0xffffffffu, rmax0, 2));
            rmax1 = fmaxf(rmax1, __shfl_xor_sync(0xffffffffu, rmax1, 1));
            rmax1 = fmaxf(rmax1, __shfl_xor_sync(0xffffffffu, rmax1, 2));
            float mn0 = fmaxf(m0a, rmax0), mn1 = fmaxf(m0b, rmax1);
            float fac0 = __expf(m0a - mn0), fac1 = __expf(m0b - mn1);
            float rs0 = 0.0f, rs1 = 0.0f;
#pragma unroll
            for (int j = 0; j < 8; j++) {
                s0[j][0] = __expf(s0[j][0] - mn0); s0[j][1] = __expf(s0[j][1] - mn0);
                s0[j][2] = __expf(s0[j][2] - mn1); s0[j][3] = __expf(s0[j][3] - mn1);
                rs0 += s0[j][0] + s0[j][1];
                rs1 += s0[j][2] + s0[j][3];
            }
            rs0 += __shfl_xor_sync(0xffffffffu, rs0, 1);
            rs0 += __shfl_xor_sync(0xffffffffu, rs0, 2);
            rs1 += __shfl_xor_sync(0xffffffffu, rs1, 1);
            rs1 += __shfl_xor_sync(0xffffffffu, rs1, 2);
            l0a = l0a * fac0 + rs0;  m0a = mn0;
            l0b = l0b * fac1 + rs1;  m0b = mn1;
#pragma unroll
            for (int j = 0; j < 8; j++) {
                o0[j][0] *= fac0; o0[j][1] *= fac0;
                o0[j][2] *= fac1; o0[j][3] *= fac1;
            }
        }
        // ---- tile 1 ----
        {
            float rmax0 = -1e30f, rmax1 = -1e30f;
#pragma unroll
            for (int j = 0; j < 8; j++) {
                float bb0 = sB[j * 8 + 2 * lc], bb1 = sB[j * 8 + 2 * lc + 1];
                s1[j][0] += bb0; s1[j][1] += bb1; s1[j][2] += bb0; s1[j][3] += bb1;
                rmax0 = fmaxf(rmax0, fmaxf(s1[j][0], s1[j][1]));
                rmax1 = fmaxf(rmax1, fmaxf(s1[j][2], s1[j][3]));
            }
            rmax0 = fmaxf(rmax0, __shfl_xor_sync(0xffffffffu, rmax0, 1));
            rmax0 = fmaxf(rmax0, __shfl_xor_sync(0xffffffffu, rmax0, 2));
            rmax1 = fmaxf(rmax1, __shfl_xor_sync(0xffffffffu, rmax1, 1));
            rmax1 = fmaxf(rmax1, __shfl_xor_sync(0xffffffffu, rmax1, 2));
            float mn0 = fmaxf(m1a, rmax0), mn1 = fmaxf(m1b, rmax1);
            float fac0 = __expf(m1a - mn0), fac1 = __expf(m1b - mn1);
            float rs0 = 0.0f, rs1 = 0.0f;
#pragma unroll
            for (int j = 0; j < 8; j++) {
                s1[j][0] = __expf(s1[j][0] - mn0); s1[j][1] = __expf(s1[j][1] - mn0);
                s1[j][2] = __expf(s1[j][2] - mn1); s1[j][3] = __expf(s1[j][3] - mn1);
                rs0 += s1[j][0] + s1[j][1];
                rs1 += s1[j][2] + s1[j][3];
            }
            rs0 += __shfl_xor_sync(0xffffffffu, rs0, 1);
            rs0 += __shfl_xor_sync(0xffffffffu, rs0, 2);
            rs1 += __shfl_xor_sync(0xffffffffu, rs1, 1);
            rs1 += __shfl_xor_sync(0xffffffffu, rs1, 2);
            l1a = l1a * fac0 + rs0;  m1a = mn0;
            l1b = l1b * fac1 + rs1;  m1b = mn1;
#pragma unroll
            for (int j = 0; j < 8; j++) {
                o1[j][0] *= fac0; o1[j][1] *= fac0;
                o1[j][2] *= fac1; o1[j][3] *= fac1;
            }
        }

        // ---- P -> bf16 hi/lo A-fragments (both tiles) ----
        uint32_t ph0[4][4], pl0[4][4], ph1[4][4], pl1[4][4];
#pragma unroll
        for (int kc = 0; kc < 4; kc++) {
            const int j0 = 2 * kc, j1 = 2 * kc + 1;
            split2(s0[j0][0], s0[j0][1], ph0[kc][0], pl0[kc][0]);
            split2(s0[j0][2], s0[j0][3], ph0[kc][1], pl0[kc][1]);
            split2(s0[j1][0], s0[j1][1], ph0[kc][2], pl0[kc][2]);
            split2(s0[j1][2], s0[j1][3], ph0[kc][3], pl0[kc][3]);
            split2(s1[j0][0], s1[j0][1], ph1[kc][0], pl1[kc][0]);
            split2(s1[j0][2], s1[j0][3], ph1[kc][1], pl1[kc][1]);
            split2(s1[j1][0], s1[j1][1], ph1[kc][2], pl1[kc][2]);
            split2(s1[j1][2], s1[j1][3], ph1[kc][3], pl1[kc][3]);
        }

        // ---- O += P V, V fragments shared across tiles ----
#pragma unroll
        for (int j = 0; j < 8; j++) {
            const uint32_t* vbh = sVh + (j * 8 + lr) * 36 + lc;
            const uint32_t* vbl = sVl + (j * 8 + lr) * 36 + lc;
#pragma unroll
            for (int kc = 0; kc < 4; kc++) {
                uint32_t bh[2] = { vbh[kc * 8], vbh[kc * 8 + 4] };
                uint32_t bl[2] = { vbl[kc * 8], vbl[kc * 8 + 4] };
                mma16816(o0[j], ph0[kc], bh);
                mma16816(o0[j], pl0[kc], bh);
                mma16816(o0[j], ph0[kc], bl);
                mma16816(o1[j], ph1[kc], bh);
                mma16816(o1[j], pl1[kc], bh);
                mma16816(o1[j], ph1[kc], bl);
            }
        }
    }

    // ---- epilogue (both tiles) ----
    const float i0a = 1.0f / l0a, i0b = 1.0f / l0b;
    const float i1a = 1.0f / l1a, i1b = 1.0f / l1b;
    const int row0 = q0 + w * 32 + lr;
#pragma unroll
    for (int j = 0; j < 8; j++) {
        const int col = j * 8 + 2 * lc;
        *(float2*)(ctx + base + (size_t)row0 * HIDN + col) =
            make_float2(o0[j][0] * i0a, o0[j][1] * i0a);
        *(float2*)(ctx + base + (size_t)(row0 + 8) * HIDN + col) =
            make_float2(o0[j][2] * i0b, o0[j][3] * i0b);
        *(float2*)(ctx + base + (size_t)(row0 + 16) * HIDN + col) =
            make_float2(o1[j][0] * i1a, o1[j][1] * i1a);
        *(float2*)(ctx + base + (size_t)(row0 + 24) * HIDN + col) =
            make_float2(o1[j][2] * i1b, o1[j][3] * i1b);
    }
}

// ---------------------------------------------------------------------------
extern "C" void kernel_launch(void* const* d_in, const int* in_sizes, int n_in,
                              void* d_out, int out_size)
{
    const float* hidden = (const float*)d_in[0];
    const float* Wq = (const float*)d_in[1];  const float* bq = (const float*)d_in[2];
    const float* Wk = (const float*)d_in[3];  const float* bk = (const float*)d_in[4];
    const float* Wv = (const float*)d_in[5];  const float* bv = (const float*)d_in[6];
    const float* Wo = (const float*)d_in[7];  const float* bo = (const float*)d_in[8];
    const float* Wpe = (const float*)d_in[9]; const float* bpe = (const float*)d_in[10];
    const float* pos_bias = (const float*)d_in[11];
    float* out = (float*)d_out;

    float *dq, *dk, *dv, *dctx;
    cudaGetSymbolAddress((void**)&dq, g_q);
    cudaGetSymbolAddress((void**)&dk, g_k);
    cudaGetSymbolAddress((void**)&dv, g_v);
    cudaGetSymbolAddress((void**)&dctx, g_ctx);
    __nv_bfloat16 *ae, *ce, *we;
    cudaGetSymbolAddress((void**)&ae, g_ae);
    cudaGetSymbolAddress((void**)&ce, g_ce);
    cudaGetSymbolAddress((void**)&we, g_we);
    __nv_bfloat16* weq = we;
    __nv_bfloat16* wek = we + (size_t)1 * HIDN * KE;
    __nv_bfloat16* wev = we + (size_t)2 * HIDN * KE;
    __nv_bfloat16* weo = we + (size_t)3 * HIDN * KE;

    cudaFuncSetAttribute(attn_tc, cudaFuncAttributeMaxDynamicSharedMemorySize, ATTN_SMEM);
    cudaFuncSetAttribute(gemm_tc, cudaFuncAttributeMaxDynamicSharedMemorySize, GEMM_SMEM);

    // convert weights + activations to hi/lo bf16 split
    prep_w<<<dim3(HIDN, 1, 4), 256>>>(Wq, Wk, Wv, Wo, weq, wek, wev, weo);
    prep_a<true><<<NTOK, 256>>>(hidden, Wpe, bpe, ae);

    // QKV projections (HMMA, cp.async pipelined)
    gemm_tc<<<dim3(8, 128, 3), 256, GEMM_SMEM>>>(ae,
                                                 weq, bq, dq,
                                                 wek, bk, dk,
                                                 wev, bv, dv);
    // tensor-core attention
    attn_tc<<<dim3(8, HH, BB), 128, ATTN_SMEM>>>(dq, dk, dv, pos_bias, dctx);

    // ctx -> split, then O projection
    prep_a<false><<<NTOK, 256>>>(dctx, nullptr, nullptr, ce);
    gemm_tc<<<dim3(8, 128, 1), 256, GEMM_SMEM>>>(ce,
                                                 weo, bo, out,
                                                 weo, bo, out,
                                                 weo, bo, out);
}